// round 14
// baseline (speedup 1.0000x reference)
#include <cuda_runtime.h>
#include <math.h>

#define HH 512
#define WW 512

// cos(k*pi/16)
#define P1 0.980785280403230449f
#define P2 0.923879532511286756f
#define P3 0.831469612302545237f
#define P4 0.707106781186547524f
#define P5 0.555570233019602225f
#define P6 0.382683432365089772f
#define P7 0.195090322016128268f

__constant__ float gQY[64] = {
  16,11,10,16,24,40,51,61,
  12,12,14,19,26,58,60,55,
  14,13,16,24,40,57,69,56,
  14,17,22,29,51,87,80,62,
  18,22,37,56,68,109,103,77,
  24,35,55,64,81,104,113,92,
  49,64,78,87,103,121,120,101,
  72,92,95,98,112,100,103,99
};
__constant__ float gQC[64] = {
  17,18,24,47,99,99,99,99,
  18,21,26,66,99,99,99,99,
  24,26,56,99,99,99,99,99,
  47,66,99,99,99,99,99,99,
  99,99,99,99,99,99,99,99,
  99,99,99,99,99,99,99,99,
  99,99,99,99,99,99,99,99,
  99,99,99,99,99,99,99,99
};

// f[v] = sum_i d[i] * cos((2i+1) v pi/16)   (even/odd butterfly form)
__device__ __forceinline__ void fdct8(const float* d, float* t)
{
    float a0=d[0]+d[7], a1=d[1]+d[6], a2=d[2]+d[5], a3=d[3]+d[4];
    float b0=d[0]-d[7], b1=d[1]-d[6], b2=d[2]-d[5], b3=d[3]-d[4];
    t[0]=(a0+a1)+(a2+a3);
    t[4]=P4*((a0+a3)-(a1+a2));
    t[2]=fmaf(a0,P2, fmaf(a1,P6, fmaf(a2,-P6, -P2*a3)));
    t[6]=fmaf(a0,P6, fmaf(a1,-P2, fmaf(a2,P2, -P6*a3)));
    t[1]=fmaf(b0,P1, fmaf(b1,P3, fmaf(b2,P5,  P7*b3)));
    t[3]=fmaf(b0,P3, fmaf(b1,-P7, fmaf(b2,-P1, -P5*b3)));
    t[5]=fmaf(b0,P5, fmaf(b1,-P1, fmaf(b2,P7,  P3*b3)));
    t[7]=fmaf(b0,P7, fmaf(b1,-P5, fmaf(b2,P3, -P1*b3)));
}

// s[u] = sum_i e[i] * cos((2u+1) i pi/16)   (even/odd butterfly form)
__device__ __forceinline__ void idct8(const float* e, float* s)
{
    float p0 = e[0] + fmaf(e[2],P2,  fmaf(e[4], P4,  P6*e[6]));
    float p1 = e[0] + fmaf(e[2],P6,  fmaf(e[4],-P4, -P2*e[6]));
    float p2 = e[0] + fmaf(e[2],-P6, fmaf(e[4],-P4,  P2*e[6]));
    float p3 = e[0] + fmaf(e[2],-P2, fmaf(e[4], P4, -P6*e[6]));
    float q0 = fmaf(e[1],P1, fmaf(e[3],P3,  fmaf(e[5],P5,  P7*e[7])));
    float q1 = fmaf(e[1],P3, fmaf(e[3],-P7, fmaf(e[5],-P1, -P5*e[7])));
    float q2 = fmaf(e[1],P5, fmaf(e[3],-P1, fmaf(e[5],P7,  P3*e[7])));
    float q3 = fmaf(e[1],P7, fmaf(e[3],-P5, fmaf(e[5],P3, -P1*e[7])));
    s[0]=p0+q0; s[7]=p0-q0;
    s[1]=p1+q1; s[6]=p1-q1;
    s[2]=p2+q2; s[5]=p2-q2;
    s[3]=p3+q3; s[4]=p3-q3;
}

// diff_round(z) = z - (1/pi) * sum_{n=1..9} ((-1)^{n+1}/n) sin(2*pi*n*z)
// Chebyshev-U collapse: sum = sin(th) * P8(cos(th))
__device__ __forceinline__ float diff_round(float z)
{
    float r  = z - rintf(z);                 // [-0.5, 0.5]
    float h  = r * 3.14159265358979324f;     // half angle in [-pi/2, pi/2]
    float h2 = h * h;

    float sh = h * fmaf(h2, fmaf(h2, fmaf(h2, fmaf(h2, 2.75573192e-6f, -1.98412698e-4f),
                                          8.33333333e-3f), -1.66666667e-1f), 1.0f);
    float ch = fmaf(h2, fmaf(h2, fmaf(h2, fmaf(h2, 2.48015873e-5f, -1.38888889e-3f),
                                      4.16666667e-2f), -5.0e-1f), 1.0f);

    float s1 = (sh + sh) * ch;               // sin(2*pi*r)
    float c  = fmaf(-2.0f * sh, sh, 1.0f);   // cos(2*pi*r)
    float c2 = c * c;

    float p = fmaf(c, 9.0541479f, -5.0929582f);
    p = fmaf(c, p, -12.9344970f);
    p = fmaf(c, p,   5.9417845f);
    p = fmaf(c, p,   5.8690280f);
    p = fmaf(c, p,  -2.1220659f);
    p = fmaf(c, p,  -0.6628930f);
    p = fmaf(c2, p,  0.2657635f);            // covers c^1 (=0) and c^0 in one step

    return z - s1 * p;
}

#define SCR_STRIDE 12    // floats per scratch row (16B-aligned rows)
#define SCR_GROUP  104   // floats per group (8-bank skew between warp groups)

__global__ void __launch_bounds__(192, 8)
djpeg_kernel(const float* __restrict__ in, float* __restrict__ out)
{
    __shared__ __align__(16) float sY  [32*36];       // luma tile (input staging only)
    __shared__ __align__(16) float sCbP[16*20];       // pooled chroma in
    __shared__ __align__(16) float sCrP[16*20];
    __shared__ __align__(16) float sCbO[16*20];       // reconstructed chroma (-128)
    __shared__ __align__(16) float sCrO[16*20];
    __shared__ __align__(16) float sScr[24*SCR_GROUP];// transpose scratch
    __shared__ __align__(16) float sZ[2][64];         // quant multipliers
    __shared__ __align__(16) float sD[2][64];         // dequant multipliers

    const int tid = threadIdx.x;
    const int b   = blockIdx.z;
    const int px0 = blockIdx.x * 32;
    const int py0 = blockIdx.y * 32;

    const float* base = in + (size_t)b * 3 * HH * WW;

    // ---- load (threads 0..127) + tables (threads 128..191) -------------
    if (tid < 128) {
        int rp = tid >> 3;              // row-pair 0..15
        int c4 = (tid & 7) << 2;        // col offset 0,4,...,28
        size_t o0 = ((size_t)(py0 + 2*rp) * WW + px0 + c4) >> 2;
        const float4* R4 = (const float4*)base;
        const float4* G4 = (const float4*)(base + HH*WW);
        const float4* B4 = (const float4*)(base + 2*HH*WW);
        float4 Ra = R4[o0], Rb = R4[o0 + WW/4];
        float4 Ga = G4[o0], Gb = G4[o0 + WW/4];
        float4 Ba = B4[o0], Bb = B4[o0 + WW/4];
        float r0[4]={Ra.x,Ra.y,Ra.z,Ra.w}, r1[4]={Rb.x,Rb.y,Rb.z,Rb.w};
        float g0[4]={Ga.x,Ga.y,Ga.z,Ga.w}, g1[4]={Gb.x,Gb.y,Gb.z,Gb.w};
        float b0[4]={Ba.x,Ba.y,Ba.z,Ba.w}, b1[4]={Bb.x,Bb.y,Bb.z,Bb.w};

        float ya[4], yb[4];
        #pragma unroll
        for (int w = 0; w < 4; w++) {
            ya[w] = fmaf(76.245f, r0[w], fmaf(149.685f, g0[w], 29.07f * b0[w]));
            yb[w] = fmaf(76.245f, r1[w], fmaf(149.685f, g1[w], 29.07f * b1[w]));
        }
        *(float4*)(sY + (2*rp  )*36 + c4) = make_float4(ya[0],ya[1],ya[2],ya[3]);
        *(float4*)(sY + (2*rp+1)*36 + c4) = make_float4(yb[0],yb[1],yb[2],yb[3]);

        float cb[2], cr[2];
        #pragma unroll
        for (int q = 0; q < 2; q++) {
            float rs = (r0[2*q]+r0[2*q+1]) + (r1[2*q]+r1[2*q+1]);
            float gs = (g0[2*q]+g0[2*q+1]) + (g1[2*q]+g1[2*q+1]);
            float bs = (b0[2*q]+b0[2*q+1]) + (b1[2*q]+b1[2*q+1]);
            // 255*0.25*coeff folded; +128 shift included
            cb[q] = fmaf(-10.75692f, rs, fmaf(-21.11808f, gs, fmaf(31.875f,   bs, 128.0f)));
            cr[q] = fmaf( 31.875f,   rs, fmaf(-26.69136f, gs, fmaf(-5.18364f, bs, 128.0f)));
        }
        *(float2*)(sCbP + rp*20 + (tid & 7)*2) = make_float2(cb[0], cb[1]);
        *(float2*)(sCrP + rp*20 + (tid & 7)*2) = make_float2(cr[0], cr[1]);
    } else {
        int i = tid - 128;              // 0..63
        int u = i & 7, v = i >> 3;
        float al = ((u==0)?0.70710678118654752f:1.0f) * ((v==0)?0.70710678118654752f:1.0f);
        float ty = gQY[i], tc = gQC[i];
        sZ[0][i] = 2.5f   * al / ty;    // 0.25*alpha / (T*0.1)
        sD[0][i] = 0.025f * al * ty;    // T*0.1*alpha*0.25
        sZ[1][i] = 2.5f   * al / tc;
        sD[1][i] = 0.025f * al * tc;
    }
    __syncthreads();

    // ---- per-block transforms: groups of 8 threads ----------------------
    const int g = tid >> 3;   // 0..15 Y, 16..19 Cb, 20..23 Cr
    const int j = tid & 7;
    const bool isY = (g < 16);

    const float* srcp;
    float* dstp = 0;
    int yr = 0, yc0 = 0;
    if (isY) {
        yr  = (g >> 2)*8 + j;
        yc0 = (g & 3)*8;
        srcp = sY + yr*36 + yc0;
    } else {
        int g2 = g & 3;
        int hy = (g2 >> 1)*8 + j, hx0 = (g2 & 1)*8;
        bool isCr = (g >= 20);
        srcp = (isCr ? sCrP : sCbP) + hy*20 + hx0;
        dstp = (isCr ? sCrO : sCbO) + hy*20 + hx0;
    }
    const float* zrow = sZ[isY ? 0 : 1] + j*8;
    const float* drow = sD[isY ? 0 : 1] + j*8;
    float* scr = sScr + g*SCR_GROUP;

    float d[8];
    {
        float4 A = *(const float4*)srcp;
        float4 B = *(const float4*)(srcp + 4);
        d[0]=A.x; d[1]=A.y; d[2]=A.z; d[3]=A.w;
        d[4]=B.x; d[5]=B.y; d[6]=B.z; d[7]=B.w;
    }

    // FWD pass 1 ( -128 level shift folded into DC only )
    float t[8];
    fdct8(d, t);
    t[0] -= 1024.0f;          // == 8 * 128 shift on the DC lane

    #pragma unroll
    for (int v = 0; v < 8; v++) scr[v*SCR_STRIDE + j] = t[v];
    __syncwarp();
    float tr[8];
    {
        float4 A = *(const float4*)(scr + j*SCR_STRIDE);
        float4 B = *(const float4*)(scr + j*SCR_STRIDE + 4);
        tr[0]=A.x; tr[1]=A.y; tr[2]=A.z; tr[3]=A.w;
        tr[4]=B.x; tr[5]=B.y; tr[6]=B.z; tr[7]=B.w;
    }
    __syncwarp();

    // FWD pass 2 + quant + diff_round + dequant
    float t2[8];
    fdct8(tr, t2);
    float e[8];
    #pragma unroll
    for (int u = 0; u < 8; u++)
        e[u] = diff_round(t2[u] * zrow[u]) * drow[u];

    // INV pass 1
    float s[8];
    idct8(e, s);
    #pragma unroll
    for (int u = 0; u < 8; u++) scr[u*SCR_STRIDE + j] = s[u];
    __syncwarp();
    float sr[8];
    {
        float4 A = *(const float4*)(scr + j*SCR_STRIDE);
        float4 B = *(const float4*)(scr + j*SCR_STRIDE + 4);
        sr[0]=A.x; sr[1]=A.y; sr[2]=A.z; sr[3]=A.w;
        sr[4]=B.x; sr[5]=B.y; sr[6]=B.z; sr[7]=B.w;
    }
    __syncwarp();

    // INV pass 2 (+128 folded into DC lane, luma only; chroma stays -128)
    if (isY) sr[0] += 128.0f;
    float p[8];
    idct8(sr, p);

    if (!isY) {
        // chroma: stage reconstructed (-128) values for the luma epilogue
        *(float4*)dstp       = make_float4(p[0],p[1],p[2],p[3]);
        *(float4*)(dstp + 4) = make_float4(p[4],p[5],p[6],p[7]);
    }
    __syncthreads();

    // ---- fused Y epilogue: color-convert + store straight from registers --
    if (isY) {
        int hy = yr >> 1, hx = yc0 >> 1;
        float4 CB = *(float4*)(sCbO + hy*20 + hx);
        float4 CR = *(float4*)(sCrO + hy*20 + hx);
        float cbv[4] = {CB.x, CB.y, CB.z, CB.w};
        float crv[4] = {CR.x, CR.y, CR.z, CR.w};

        float* ob = out + (size_t)b * 3 * HH * WW;
        size_t off = ((size_t)(py0 + yr) * WW + px0 + yc0) >> 2;
        float4* oR = (float4*)ob + off;
        float4* oG = (float4*)(ob + HH*WW) + off;
        float4* oB = (float4*)(ob + 2*HH*WW) + off;

        #pragma unroll
        for (int hf = 0; hf < 2; hf++) {
            float r4[4], g4[4], b4[4];
            #pragma unroll
            for (int w = 0; w < 4; w++) {
                int v = hf*4 + w;
                float cb = cbv[v >> 1], cr = crv[v >> 1];
                float yn = p[v] * 0.0039215686f;                    // y/255
                r4[w] = __saturatef(fmaf(cr,  0.0054980392f, yn));
                g4[w] = __saturatef(fmaf(cr, -0.0028005333f,
                                     fmaf(cb, -0.0013495529f, yn)));
                b4[w] = __saturatef(fmaf(cb,  0.0069490196f, yn));
            }
            oR[hf] = make_float4(r4[0],r4[1],r4[2],r4[3]);
            oG[hf] = make_float4(g4[0],g4[1],g4[2],g4[3]);
            oB[hf] = make_float4(b4[0],b4[1],b4[2],b4[3]);
        }
    }
}

extern "C" void kernel_launch(void* const* d_in, const int* in_sizes, int n_in,
                              void* d_out, int out_size)
{
    const float* x = (const float*)d_in[0];
    float* y = (float*)d_out;
    int Bn = in_sizes[0] / (3 * HH * WW);
    dim3 grid(WW / 32, HH / 32, Bn);
    djpeg_kernel<<<grid, 192>>>(x, y);
}

// round 15
// speedup vs baseline: 1.2695x; 1.2695x over previous
#include <cuda_runtime.h>
#include <math.h>

#define HH 512
#define WW 512

// cos(k*pi/16)
#define P1 0.980785280403230449f
#define P2 0.923879532511286756f
#define P3 0.831469612302545237f
#define P4 0.707106781186547524f
#define P5 0.555570233019602225f
#define P6 0.382683432365089772f
#define P7 0.195090322016128268f

__constant__ float gQY[64] = {
  16,11,10,16,24,40,51,61,
  12,12,14,19,26,58,60,55,
  14,13,16,24,40,57,69,56,
  14,17,22,29,51,87,80,62,
  18,22,37,56,68,109,103,77,
  24,35,55,64,81,104,113,92,
  49,64,78,87,103,121,120,101,
  72,92,95,98,112,100,103,99
};
__constant__ float gQC[64] = {
  17,18,24,47,99,99,99,99,
  18,21,26,66,99,99,99,99,
  24,26,56,99,99,99,99,99,
  47,66,99,99,99,99,99,99,
  99,99,99,99,99,99,99,99,
  99,99,99,99,99,99,99,99,
  99,99,99,99,99,99,99,99,
  99,99,99,99,99,99,99,99
};

// f[v] = sum_i d[i] * cos((2i+1) v pi/16)   (even/odd butterfly form)
__device__ __forceinline__ void fdct8(const float* d, float* t)
{
    float a0=d[0]+d[7], a1=d[1]+d[6], a2=d[2]+d[5], a3=d[3]+d[4];
    float b0=d[0]-d[7], b1=d[1]-d[6], b2=d[2]-d[5], b3=d[3]-d[4];
    t[0]=(a0+a1)+(a2+a3);
    t[4]=P4*((a0+a3)-(a1+a2));
    t[2]=fmaf(a0,P2, fmaf(a1,P6, fmaf(a2,-P6, -P2*a3)));
    t[6]=fmaf(a0,P6, fmaf(a1,-P2, fmaf(a2,P2, -P6*a3)));
    t[1]=fmaf(b0,P1, fmaf(b1,P3, fmaf(b2,P5,  P7*b3)));
    t[3]=fmaf(b0,P3, fmaf(b1,-P7, fmaf(b2,-P1, -P5*b3)));
    t[5]=fmaf(b0,P5, fmaf(b1,-P1, fmaf(b2,P7,  P3*b3)));
    t[7]=fmaf(b0,P7, fmaf(b1,-P5, fmaf(b2,P3, -P1*b3)));
}

// s[u] = sum_i e[i] * cos((2u+1) i pi/16)   (even/odd butterfly form)
__device__ __forceinline__ void idct8(const float* e, float* s)
{
    float p0 = e[0] + fmaf(e[2],P2,  fmaf(e[4], P4,  P6*e[6]));
    float p1 = e[0] + fmaf(e[2],P6,  fmaf(e[4],-P4, -P2*e[6]));
    float p2 = e[0] + fmaf(e[2],-P6, fmaf(e[4],-P4,  P2*e[6]));
    float p3 = e[0] + fmaf(e[2],-P2, fmaf(e[4], P4, -P6*e[6]));
    float q0 = fmaf(e[1],P1, fmaf(e[3],P3,  fmaf(e[5],P5,  P7*e[7])));
    float q1 = fmaf(e[1],P3, fmaf(e[3],-P7, fmaf(e[5],-P1, -P5*e[7])));
    float q2 = fmaf(e[1],P5, fmaf(e[3],-P1, fmaf(e[5],P7,  P3*e[7])));
    float q3 = fmaf(e[1],P7, fmaf(e[3],-P5, fmaf(e[5],P3, -P1*e[7])));
    s[0]=p0+q0; s[7]=p0-q0;
    s[1]=p1+q1; s[6]=p1-q1;
    s[2]=p2+q2; s[5]=p2-q2;
    s[3]=p3+q3; s[4]=p3-q3;
}

// diff_round(z) = z - (1/pi) * sum_{n=1..9} ((-1)^{n+1}/n) sin(2*pi*n*z)
// Chebyshev-U collapse: sum = sin(th) * P8(cos(th)); sin/cos via MUFU.
__device__ __forceinline__ float diff_round(float z)
{
    float r  = z - rintf(z);                 // [-0.5, 0.5]
    float th = r * 6.28318530717958648f;     // [-pi, pi]
    float s1 = __sinf(th);                   // MUFU.SIN
    float c  = __cosf(th);                   // MUFU.COS
    float c2 = c * c;

    float p = fmaf(c, 9.0541479f, -5.0929582f);
    p = fmaf(c, p, -12.9344970f);
    p = fmaf(c, p,   5.9417845f);
    p = fmaf(c, p,   5.8690280f);
    p = fmaf(c, p,  -2.1220659f);
    p = fmaf(c, p,  -0.6628930f);
    p = fmaf(c2, p,  0.2657635f);            // covers c^1 (=0) and c^0 in one step

    return z - s1 * p;
}

#define SCR_STRIDE 12    // floats per scratch row (16B-aligned rows)
#define SCR_GROUP  104   // floats per group (8-bank skew between warp groups)

__global__ void __launch_bounds__(192, 8)
djpeg_kernel(const float* __restrict__ in, float* __restrict__ out)
{
    __shared__ __align__(16) float sY  [32*36];       // luma tile, row stride 36
    __shared__ __align__(16) float sCbP[16*20];       // pooled chroma in
    __shared__ __align__(16) float sCrP[16*20];
    __shared__ __align__(16) float sCbO[16*20];       // reconstructed chroma (-128)
    __shared__ __align__(16) float sCrO[16*20];
    __shared__ __align__(16) float sScr[24*SCR_GROUP];// transpose scratch
    __shared__ __align__(16) float sZ[2][64];         // quant multipliers
    __shared__ __align__(16) float sD[2][64];         // dequant multipliers

    const int tid = threadIdx.x;
    const int b   = blockIdx.z;
    const int px0 = blockIdx.x * 32;
    const int py0 = blockIdx.y * 32;

    const float* base = in + (size_t)b * 3 * HH * WW;

    // ---- load (threads 0..127) + tables (threads 128..191) -------------
    if (tid < 128) {
        int rp = tid >> 3;              // row-pair 0..15
        int c4 = (tid & 7) << 2;        // col offset 0,4,...,28
        size_t o0 = ((size_t)(py0 + 2*rp) * WW + px0 + c4) >> 2;
        const float4* R4 = (const float4*)base;
        const float4* G4 = (const float4*)(base + HH*WW);
        const float4* B4 = (const float4*)(base + 2*HH*WW);
        float4 Ra = R4[o0], Rb = R4[o0 + WW/4];
        float4 Ga = G4[o0], Gb = G4[o0 + WW/4];
        float4 Ba = B4[o0], Bb = B4[o0 + WW/4];
        float r0[4]={Ra.x,Ra.y,Ra.z,Ra.w}, r1[4]={Rb.x,Rb.y,Rb.z,Rb.w};
        float g0[4]={Ga.x,Ga.y,Ga.z,Ga.w}, g1[4]={Gb.x,Gb.y,Gb.z,Gb.w};
        float b0[4]={Ba.x,Ba.y,Ba.z,Ba.w}, b1[4]={Bb.x,Bb.y,Bb.z,Bb.w};

        float ya[4], yb[4];
        #pragma unroll
        for (int w = 0; w < 4; w++) {
            ya[w] = fmaf(76.245f, r0[w], fmaf(149.685f, g0[w], 29.07f * b0[w]));
            yb[w] = fmaf(76.245f, r1[w], fmaf(149.685f, g1[w], 29.07f * b1[w]));
        }
        *(float4*)(sY + (2*rp  )*36 + c4) = make_float4(ya[0],ya[1],ya[2],ya[3]);
        *(float4*)(sY + (2*rp+1)*36 + c4) = make_float4(yb[0],yb[1],yb[2],yb[3]);

        float cb[2], cr[2];
        #pragma unroll
        for (int q = 0; q < 2; q++) {
            float rs = (r0[2*q]+r0[2*q+1]) + (r1[2*q]+r1[2*q+1]);
            float gs = (g0[2*q]+g0[2*q+1]) + (g1[2*q]+g1[2*q+1]);
            float bs = (b0[2*q]+b0[2*q+1]) + (b1[2*q]+b1[2*q+1]);
            // 255*0.25*coeff folded; +128 shift included
            cb[q] = fmaf(-10.75692f, rs, fmaf(-21.11808f, gs, fmaf(31.875f,   bs, 128.0f)));
            cr[q] = fmaf( 31.875f,   rs, fmaf(-26.69136f, gs, fmaf(-5.18364f, bs, 128.0f)));
        }
        *(float2*)(sCbP + rp*20 + (tid & 7)*2) = make_float2(cb[0], cb[1]);
        *(float2*)(sCrP + rp*20 + (tid & 7)*2) = make_float2(cr[0], cr[1]);
    } else {
        int i = tid - 128;              // 0..63
        int u = i & 7, v = i >> 3;
        float al = ((u==0)?0.70710678118654752f:1.0f) * ((v==0)?0.70710678118654752f:1.0f);
        float ty = gQY[i], tc = gQC[i];
        sZ[0][i] = 2.5f   * al / ty;    // 0.25*alpha / (T*0.1)
        sD[0][i] = 0.025f * al * ty;    // T*0.1*alpha*0.25
        sZ[1][i] = 2.5f   * al / tc;
        sD[1][i] = 0.025f * al * tc;
    }
    __syncthreads();

    // ---- per-block transforms: groups of 8 threads ----------------------
    const int g = tid >> 3;   // 0..15 Y, 16..19 Cb, 20..23 Cr
    const int j = tid & 7;
    const bool isY = (g < 16);

    const float* srcp;
    float* dstp;
    if (isY) {
        int yr = (g >> 2)*8 + j;
        float* p = sY + yr*36 + (g & 3)*8;
        srcp = p; dstp = p;
    } else {
        int g2 = g & 3;
        int hy = (g2 >> 1)*8 + j, hx0 = (g2 & 1)*8;
        bool isCr = (g >= 20);
        srcp = (isCr ? sCrP : sCbP) + hy*20 + hx0;
        dstp = (isCr ? sCrO : sCbO) + hy*20 + hx0;
    }
    const float* zrow = sZ[isY ? 0 : 1] + j*8;
    const float* drow = sD[isY ? 0 : 1] + j*8;
    float* scr = sScr + g*SCR_GROUP;

    float d[8];
    {
        float4 A = *(const float4*)srcp;
        float4 B = *(const float4*)(srcp + 4);
        d[0]=A.x; d[1]=A.y; d[2]=A.z; d[3]=A.w;
        d[4]=B.x; d[5]=B.y; d[6]=B.z; d[7]=B.w;
    }

    // FWD pass 1 ( -128 level shift folded into DC only )
    float t[8];
    fdct8(d, t);
    t[0] -= 1024.0f;          // == 8 * 128 shift on the DC lane

    #pragma unroll
    for (int v = 0; v < 8; v++) scr[v*SCR_STRIDE + j] = t[v];
    __syncwarp();
    float tr[8];
    {
        float4 A = *(const float4*)(scr + j*SCR_STRIDE);
        float4 B = *(const float4*)(scr + j*SCR_STRIDE + 4);
        tr[0]=A.x; tr[1]=A.y; tr[2]=A.z; tr[3]=A.w;
        tr[4]=B.x; tr[5]=B.y; tr[6]=B.z; tr[7]=B.w;
    }
    __syncwarp();

    // FWD pass 2 + quant + diff_round + dequant
    float t2[8];
    fdct8(tr, t2);
    float e[8];
    #pragma unroll
    for (int u = 0; u < 8; u++)
        e[u] = diff_round(t2[u] * zrow[u]) * drow[u];

    // INV pass 1
    float s[8];
    idct8(e, s);
    #pragma unroll
    for (int u = 0; u < 8; u++) scr[u*SCR_STRIDE + j] = s[u];
    __syncwarp();
    float sr[8];
    {
        float4 A = *(const float4*)(scr + j*SCR_STRIDE);
        float4 B = *(const float4*)(scr + j*SCR_STRIDE + 4);
        sr[0]=A.x; sr[1]=A.y; sr[2]=A.z; sr[3]=A.w;
        sr[4]=B.x; sr[5]=B.y; sr[6]=B.z; sr[7]=B.w;
    }
    __syncwarp();

    // INV pass 2 (+128 folded into DC lane, luma only; chroma stays -128)
    if (isY) sr[0] += 128.0f;
    float p[8];
    idct8(sr, p);
    *(float4*)dstp       = make_float4(p[0],p[1],p[2],p[3]);
    *(float4*)(dstp + 4) = make_float4(p[4],p[5],p[6],p[7]);

    __syncthreads();

    // ---- YCbCr->RGB with 1/255 folded, saturate, store -------------------
    float* ob = out + (size_t)b * 3 * HH * WW;
    float4* oR = (float4*)ob;
    float4* oG = (float4*)(ob + HH*WW);
    float4* oB = (float4*)(ob + 2*HH*WW);

    #pragma unroll
    for (int it = 0; it < 2; it++) {
        int ti = tid + it*192;
        if (ti < 256) {
            int py = ti >> 3, c4 = (ti & 7) << 2;
            float4 Y4 = *(float4*)(sY + py*36 + c4);
            float2 CB = *(float2*)(sCbO + (py >> 1)*20 + (c4 >> 1));
            float2 CR = *(float2*)(sCrO + (py >> 1)*20 + (c4 >> 1));
            float yv[4] = {Y4.x, Y4.y, Y4.z, Y4.w};
            float cb[4] = {CB.x, CB.x, CB.y, CB.y};
            float cr[4] = {CR.x, CR.x, CR.y, CR.y};
            float R[4], G[4], Bz[4];
            #pragma unroll
            for (int w = 0; w < 4; w++) {
                float yn = yv[w] * 0.0039215686f;                    // y/255
                R[w]  = __saturatef(fmaf(cr[w],  0.0054980392f, yn));
                G[w]  = __saturatef(fmaf(cr[w], -0.0028005333f,
                                    fmaf(cb[w], -0.0013495529f, yn)));
                Bz[w] = __saturatef(fmaf(cb[w],  0.0069490196f, yn));
            }
            size_t off = ((size_t)(py0 + py) * WW + px0 + c4) >> 2;
            oR[off] = make_float4(R[0],R[1],R[2],R[3]);
            oG[off] = make_float4(G[0],G[1],G[2],G[3]);
            oB[off] = make_float4(Bz[0],Bz[1],Bz[2],Bz[3]);
        }
    }
}

extern "C" void kernel_launch(void* const* d_in, const int* in_sizes, int n_in,
                              void* d_out, int out_size)
{
    const float* x = (const float*)d_in[0];
    float* y = (float*)d_out;
    int Bn = in_sizes[0] / (3 * HH * WW);
    dim3 grid(WW / 32, HH / 32, Bn);
    djpeg_kernel<<<grid, 192>>>(x, y);
}